// round 1
// baseline (speedup 1.0000x reference)
#include <cuda_runtime.h>
#include <cstdint>

#define D 128
#define MGRAPHS 4096
#define SLAB 512

// Scratch: per-graph pooled sums (2 MB) + seg dtype flag.
__device__ float g_pool[MGRAPHS * D];
__device__ int   g_seg_is_64;

// ---------------------------------------------------------------------------
// Probe: decide whether seg is int64 or int32.
// If underlying data is int64 (values < 2^31), the int32 view at odd indices
// is the zero high word; index N-1 (N even -> odd index) == 0.
// If underlying data is int32 (sorted, ~uniform 0..4095), last value != 0 whp.
__global__ void probe_seg_kernel(const int* seg32, int n) {
    if (threadIdx.x == 0 && blockIdx.x == 0) {
        g_seg_is_64 = (seg32[n - 1] == 0) ? 1 : 0;
    }
}

__device__ __forceinline__ long long load_seg(const void* seg, long long i) {
    if (g_seg_is_64) {
        return ((const long long*)seg)[i];
    } else {
        return (long long)((const int*)seg)[i];
    }
}

// ---------------------------------------------------------------------------
// Zero the pool scratch.
__global__ void zero_pool_kernel() {
    int i = blockIdx.x * blockDim.x + threadIdx.x;
    if (i < MGRAPHS * D) g_pool[i] = 0.0f;
}

// ---------------------------------------------------------------------------
// Segment sum: block b owns rows [b*SLAB, b*SLAB+SLAB). Thread d owns column d.
// seg is sorted, so each block spans only ~2-3 distinct segments; accumulate
// runs in a register and flush with atomicAdd at run boundaries.
__global__ void __launch_bounds__(D) seg_sum_kernel(
    const float* __restrict__ h, const void* __restrict__ seg, int n)
{
    const int d = threadIdx.x;
    long long r0 = (long long)blockIdx.x * SLAB;
    long long r1 = r0 + SLAB;
    if (r1 > n) r1 = n;
    if (r0 >= r1) return;

    float acc = 0.0f;
    long long cur = load_seg(seg, r0);

    for (long long r = r0; r < r1; ++r) {
        long long s = load_seg(seg, r);   // uniform across block -> broadcast
        if (s != cur) {
            atomicAdd(&g_pool[cur * D + d], acc);
            acc = 0.0f;
            cur = s;
        }
        acc += h[r * D + d];              // coalesced 512B per row
    }
    atomicAdd(&g_pool[cur * D + d], acc);
}

// ---------------------------------------------------------------------------
// Virtual-node FC: per graph m, x = vn_h[m] + pool[m];
// vn_new[m] = vn_h[m] + relu(x @ W^T + b). One block per graph, thread d
// computes output feature d via a float4-vectorized dot with W[d, :].
__global__ void __launch_bounds__(D) vn_fc_kernel(
    const float* __restrict__ vn_h, const float* __restrict__ W,
    const float* __restrict__ b, float* __restrict__ vn_out)
{
    const int m = blockIdx.x;
    const int d = threadIdx.x;

    __shared__ float xs[D];
    float vh = vn_h[(long long)m * D + d];
    xs[d] = vh + g_pool[m * D + d];
    __syncthreads();

    const float4* w4 = (const float4*)(W + (long long)d * D);
    float acc = 0.0f;
#pragma unroll
    for (int k4 = 0; k4 < D / 4; ++k4) {
        float4 wv = w4[k4];
        acc += wv.x * xs[4 * k4 + 0];
        acc += wv.y * xs[4 * k4 + 1];
        acc += wv.z * xs[4 * k4 + 2];
        acc += wv.w * xs[4 * k4 + 3];
    }
    acc += b[d];
    vn_out[(long long)m * D + d] = vh + fmaxf(acc, 0.0f);
}

// ---------------------------------------------------------------------------
// Broadcast add: h_new[i, :] = h[i, :] + vn_new[seg[i], :].
// One float4 (16B) per thread; 32 float4 per row. vn_new (2 MB) is L2-resident.
__global__ void __launch_bounds__(256) broadcast_add_kernel(
    const float* __restrict__ h, const void* __restrict__ seg,
    const float* __restrict__ vn_new, float* __restrict__ h_out,
    long long total4)
{
    long long i = (long long)blockIdx.x * blockDim.x + threadIdx.x;
    if (i >= total4) return;
    long long row = i >> 5;       // D/4 = 32 float4 per row
    int c = (int)(i & 31);
    long long s = load_seg(seg, row);

    float4 hv = ((const float4*)h)[i];
    float4 vv = ((const float4*)vn_new)[s * 32 + c];
    hv.x += vv.x; hv.y += vv.y; hv.z += vv.z; hv.w += vv.w;
    ((float4*)h_out)[i] = hv;
}

// ---------------------------------------------------------------------------
extern "C" void kernel_launch(void* const* d_in, const int* in_sizes, int n_in,
                              void* d_out, int out_size)
{
    const float* h    = (const float*)d_in[0];
    const float* vn_h = (const float*)d_in[1];
    const void*  seg  = d_in[2];
    const float* W    = (const float*)d_in[3];
    const float* b    = (const float*)d_in[4];

    const int n = in_sizes[0] / D;           // number of nodes (1,000,000)

    float* h_out  = (float*)d_out;
    float* vn_out = (float*)d_out + (long long)n * D;

    probe_seg_kernel<<<1, 32>>>((const int*)seg, n);
    zero_pool_kernel<<<(MGRAPHS * D + 255) / 256, 256>>>();

    int seg_blocks = (n + SLAB - 1) / SLAB;
    seg_sum_kernel<<<seg_blocks, D>>>(h, seg, n);

    vn_fc_kernel<<<MGRAPHS, D>>>(vn_h, W, b, vn_out);

    long long total4 = (long long)n * (D / 4);
    int bblocks = (int)((total4 + 255) / 256);
    broadcast_add_kernel<<<bblocks, 256>>>(h, seg, vn_out, h_out, total4);
}

// round 2
// speedup vs baseline: 1.8507x; 1.8507x over previous
#include <cuda_runtime.h>
#include <cstdint>

#define D 128
#define MGRAPHS 4096
#define GPB 32          // graphs per block in vn_fc

// Scratch (no allocation allowed): pooled sums, transposed W, segment bounds, dtype flag.
__device__ float g_pool[MGRAPHS * D];
__device__ float g_wt[D * D];              // wt[k*D + d] = W[d*D + k]
__device__ int   g_start[MGRAPHS + 1];
__device__ int   g_seg_is_64;

// ---------------------------------------------------------------------------
// Probe seg dtype. For int64 data (values < 2^31), the int32 view at odd index
// n-1 is a zero high word; for sorted int32 data the last value is ~4095 != 0.
__global__ void probe_seg_kernel(const int* seg32, int n) {
    if (threadIdx.x == 0 && blockIdx.x == 0)
        g_seg_is_64 = (seg32[n - 1] == 0) ? 1 : 0;
}

__device__ __forceinline__ long long load_seg(const void* seg, long long i) {
    return g_seg_is_64 ? ((const long long*)seg)[i]
                       : (long long)((const int*)seg)[i];
}

// ---------------------------------------------------------------------------
// Per-graph start offsets via binary search (seg is sorted). g_start[M] = n.
__global__ void seg_bounds_kernel(const void* __restrict__ seg, int n) {
    int m = blockIdx.x * blockDim.x + threadIdx.x;
    if (m > MGRAPHS) return;
    long long lo = 0, hi = n;
    while (lo < hi) {
        long long mid = (lo + hi) >> 1;
        if (load_seg(seg, mid) < (long long)m) lo = mid + 1; else hi = mid;
    }
    g_start[m] = (int)lo;
}

// ---------------------------------------------------------------------------
// One-time W transpose into g_wt (64 KB; scattered writes absorbed by L2).
__global__ void transpose_w_kernel(const float* __restrict__ W) {
    int i = blockIdx.x * blockDim.x + threadIdx.x;
    if (i < D * D) g_wt[(i % D) * D + (i / D)] = W[i];
}

// ---------------------------------------------------------------------------
// Segment sum, one block per graph over its contiguous row range.
// Thread d owns column d (coalesced 512B/row). 4 accumulators for MLP.
// No atomics, no seg loads, no branches in the hot loop.
__global__ void __launch_bounds__(D) seg_sum_kernel(const float* __restrict__ h) {
    const int m = blockIdx.x;
    const int d = threadIdx.x;
    int s = g_start[m], e = g_start[m + 1];

    float a0 = 0.f, a1 = 0.f, a2 = 0.f, a3 = 0.f;
    const float* p = h + (long long)s * D + d;
    int r = s;
    for (; r + 4 <= e; r += 4) {
        a0 += __ldcs(p + 0 * D);
        a1 += __ldcs(p + 1 * D);
        a2 += __ldcs(p + 2 * D);
        a3 += __ldcs(p + 3 * D);
        p += 4 * D;
    }
    for (; r < e; ++r) { a0 += __ldcs(p); p += D; }
    g_pool[m * D + d] = (a0 + a1) + (a2 + a3);
}

// ---------------------------------------------------------------------------
// Virtual-node FC as an outer-product micro-GEMM.
// Block: 256 threads = 32 d-groups x 8 graph-groups; GPB=32 graphs/block.
// Thread (dg, gq) computes d in {dg, dg+32, dg+64, dg+96} x 4 graphs.
// wt_s[k*D + dg + 32j] reads are lane-consecutive -> conflict-free.
// xs[g*D + k] reads are warp-uniform broadcasts.
extern __shared__ float smem_dyn[];
__global__ void __launch_bounds__(256) vn_fc_kernel(
    const float* __restrict__ vn_h, const float* __restrict__ b,
    float* __restrict__ vn_out)
{
    float* wt_s = smem_dyn;            // D*D floats (64 KB)
    float* xs   = smem_dyn + D * D;    // GPB*D floats (16 KB)

    const int t  = threadIdx.x;
    const int m0 = blockIdx.x * GPB;

    // Stage transposed W into smem (identical layout, fully coalesced).
    for (int i = t; i < D * D / 4; i += 256)
        ((float4*)wt_s)[i] = ((const float4*)g_wt)[i];

    // xs[g][:] = vn_h[m0+g][:] + pool[m0+g][:]
    for (int i = t; i < GPB * D / 4; i += 256) {
        int g = i >> 5, c = i & 31;
        float4 v = ((const float4*)(vn_h + (long long)(m0 + g) * D))[c];
        float4 p = ((const float4*)(g_pool + (long long)(m0 + g) * D))[c];
        float4 x;
        x.x = v.x + p.x; x.y = v.y + p.y; x.z = v.z + p.z; x.w = v.w + p.w;
        ((float4*)xs)[i] = x;
    }
    __syncthreads();

    const int dg = t & 31;
    const int gq = t >> 5;

    float acc[4][4];
#pragma unroll
    for (int gi = 0; gi < 4; ++gi)
#pragma unroll
        for (int j = 0; j < 4; ++j) acc[gi][j] = 0.f;

#pragma unroll 4
    for (int k = 0; k < D; ++k) {
        const float* wr = wt_s + k * D + dg;
        float w0 = wr[0], w1 = wr[32], w2 = wr[64], w3 = wr[96];
#pragma unroll
        for (int gi = 0; gi < 4; ++gi) {
            float x = xs[(gq * 4 + gi) * D + k];
            acc[gi][0] += w0 * x;
            acc[gi][1] += w1 * x;
            acc[gi][2] += w2 * x;
            acc[gi][3] += w3 * x;
        }
    }

#pragma unroll
    for (int gi = 0; gi < 4; ++gi) {
        int m = m0 + gq * 4 + gi;
#pragma unroll
        for (int j = 0; j < 4; ++j) {
            int d = dg + 32 * j;
            float vh = vn_h[(long long)m * D + d];
            vn_out[(long long)m * D + d] = vh + fmaxf(acc[gi][j] + b[d], 0.f);
        }
    }
}

// ---------------------------------------------------------------------------
// Broadcast add: h_new[i,:] = h[i,:] + vn_new[seg[i],:]. One float4/thread.
// Streaming hints keep vn_new (2 MB) + seg resident in L2 against the 1 GB stream.
__global__ void __launch_bounds__(256) broadcast_add_kernel(
    const float* __restrict__ h, const void* __restrict__ seg,
    const float* __restrict__ vn_new, float* __restrict__ h_out,
    long long total4)
{
    long long i = (long long)blockIdx.x * blockDim.x + threadIdx.x;
    if (i >= total4) return;
    long long row = i >> 5;     // 32 float4 per row
    int c = (int)(i & 31);
    long long s = load_seg(seg, row);

    const float4* hv4 = (const float4*)h;
    float4 hv;
    {
        const float4* p = hv4 + i;
        hv.x = __ldcs(&p->x); // fallback scalar path avoided: use vector ldcs below
    }
    hv = __ldcs(((const float4*)h) + i);
    float4 vv = ((const float4*)vn_new)[s * 32 + c];
    hv.x += vv.x; hv.y += vv.y; hv.z += vv.z; hv.w += vv.w;
    __stcs(((float4*)h_out) + i, hv);
}

// ---------------------------------------------------------------------------
extern "C" void kernel_launch(void* const* d_in, const int* in_sizes, int n_in,
                              void* d_out, int out_size)
{
    const float* h    = (const float*)d_in[0];
    const float* vn_h = (const float*)d_in[1];
    const void*  seg  = d_in[2];
    const float* W    = (const float*)d_in[3];
    const float* b    = (const float*)d_in[4];

    const int n = in_sizes[0] / D;                 // 1,000,000 nodes

    float* h_out  = (float*)d_out;
    float* vn_out = (float*)d_out + (long long)n * D;

    probe_seg_kernel<<<1, 32>>>((const int*)seg, n);
    seg_bounds_kernel<<<(MGRAPHS + 1 + 255) / 256, 256>>>(seg, n);
    transpose_w_kernel<<<(D * D + 255) / 256, 256>>>(W);

    seg_sum_kernel<<<MGRAPHS, D>>>(h);

    static int smem_set = 0;
    const int smem_bytes = (D * D + GPB * D) * (int)sizeof(float);
    if (!smem_set) {
        cudaFuncSetAttribute(vn_fc_kernel,
                             cudaFuncAttributeMaxDynamicSharedMemorySize,
                             smem_bytes);
        smem_set = 1;
    }
    vn_fc_kernel<<<MGRAPHS / GPB, 256, smem_bytes>>>(vn_h, b, vn_out);

    long long total4 = (long long)n * (D / 4);
    int bblocks = (int)((total4 + 255) / 256);
    broadcast_add_kernel<<<bblocks, 256>>>(h, seg, vn_out, h_out, total4);
}

// round 3
// speedup vs baseline: 1.9146x; 1.0345x over previous
#include <cuda_runtime.h>
#include <cstdint>

#define D 128
#define MGRAPHS 4096
#define GPB 32          // graphs per block in vn_fc

// Scratch (no allocation allowed).
__device__ float g_pool[MGRAPHS * D];
__device__ float g_wt[D * D];              // wt[k*D + d] = W[d*D + k]
__device__ int   g_start[MGRAPHS + 1];
__device__ int   g_seg_is_64;

// ---------------------------------------------------------------------------
// seg dtype detection: for int64 data (values < 2^31) the int32 view at odd
// index n-1 is a zero high word; for sorted int32 data the last value != 0.
__device__ __forceinline__ int detect_is64(const void* seg, int n) {
    return (((const int*)seg)[n - 1] == 0) ? 1 : 0;
}

__device__ __forceinline__ long long load_seg_w(const void* seg, long long i, int is64) {
    return is64 ? ((const long long*)seg)[i] : (long long)((const int*)seg)[i];
}

// ---------------------------------------------------------------------------
// Fused prep: blocks [0,16] compute per-graph bounds via binary search;
// blocks [17,80] transpose W; block 0/thread 0 publishes the dtype flag.
__global__ void __launch_bounds__(256) prep_kernel(
    const void* __restrict__ seg, const float* __restrict__ W, int n)
{
    if (blockIdx.x < 17) {
        int m = blockIdx.x * 256 + threadIdx.x;
        if (blockIdx.x == 0 && threadIdx.x == 0)
            g_seg_is_64 = detect_is64(seg, n);
        if (m > MGRAPHS) return;
        int is64 = detect_is64(seg, n);          // local, no dependence on flag
        long long lo = 0, hi = n;
        while (lo < hi) {
            long long mid = (lo + hi) >> 1;
            if (load_seg_w(seg, mid, is64) < (long long)m) lo = mid + 1; else hi = mid;
        }
        g_start[m] = (int)lo;
    } else {
        int i = (blockIdx.x - 17) * 256 + threadIdx.x;
        if (i < D * D) g_wt[(i % D) * D + (i / D)] = W[i];
    }
}

// ---------------------------------------------------------------------------
// Segment sum, one block (256 thr) per graph. Lane-group of 32 covers one row
// as 32 float4 (512B, coalesced); 8 row-groups per block; 4 independent
// float4 accumulators per thread -> 128B in flight per thread.
__global__ void __launch_bounds__(256) seg_sum_kernel(const float* __restrict__ h) {
    const int m    = blockIdx.x;
    const int lane = threadIdx.x & 31;
    const int rg   = threadIdx.x >> 5;          // row group 0..7
    const int s = g_start[m], e = g_start[m + 1];

    const float4* base = (const float4*)h;      // row r, chunk lane: r*32 + lane

    float4 a0 = {0,0,0,0}, a1 = {0,0,0,0}, a2 = {0,0,0,0}, a3 = {0,0,0,0};
    int r = s + rg;
    for (; r + 24 < e; r += 32) {
        float4 v0 = __ldcs(base + (long long)(r     ) * 32 + lane);
        float4 v1 = __ldcs(base + (long long)(r +  8) * 32 + lane);
        float4 v2 = __ldcs(base + (long long)(r + 16) * 32 + lane);
        float4 v3 = __ldcs(base + (long long)(r + 24) * 32 + lane);
        a0.x += v0.x; a0.y += v0.y; a0.z += v0.z; a0.w += v0.w;
        a1.x += v1.x; a1.y += v1.y; a1.z += v1.z; a1.w += v1.w;
        a2.x += v2.x; a2.y += v2.y; a2.z += v2.z; a2.w += v2.w;
        a3.x += v3.x; a3.y += v3.y; a3.z += v3.z; a3.w += v3.w;
    }
    for (; r < e; r += 8) {
        float4 v = __ldcs(base + (long long)r * 32 + lane);
        a0.x += v.x; a0.y += v.y; a0.z += v.z; a0.w += v.w;
    }
    a0.x += a1.x + a2.x + a3.x;
    a0.y += a1.y + a2.y + a3.y;
    a0.z += a1.z + a2.z + a3.z;
    a0.w += a1.w + a2.w + a3.w;

    // Reduce the 8 row-groups through smem.
    __shared__ float4 red[8][32];
    red[rg][lane] = a0;
    __syncthreads();
    if (rg == 0) {
        float4 t = red[0][lane];
#pragma unroll
        for (int g = 1; g < 8; ++g) {
            float4 u = red[g][lane];
            t.x += u.x; t.y += u.y; t.z += u.z; t.w += u.w;
        }
        ((float4*)g_pool)[m * 32 + lane] = t;
    }
}

// ---------------------------------------------------------------------------
// Virtual-node FC as an outer-product micro-GEMM (unchanged from R2; ~8us).
extern __shared__ float smem_dyn[];
__global__ void __launch_bounds__(256) vn_fc_kernel(
    const float* __restrict__ vn_h, const float* __restrict__ b,
    float* __restrict__ vn_out)
{
    float* wt_s = smem_dyn;            // D*D floats (64 KB)
    float* xs   = smem_dyn + D * D;    // GPB*D floats (16 KB)

    const int t  = threadIdx.x;
    const int m0 = blockIdx.x * GPB;

    for (int i = t; i < D * D / 4; i += 256)
        ((float4*)wt_s)[i] = ((const float4*)g_wt)[i];

    for (int i = t; i < GPB * D / 4; i += 256) {
        int g = i >> 5, c = i & 31;
        float4 v = ((const float4*)(vn_h + (long long)(m0 + g) * D))[c];
        float4 p = ((const float4*)(g_pool + (long long)(m0 + g) * D))[c];
        float4 x;
        x.x = v.x + p.x; x.y = v.y + p.y; x.z = v.z + p.z; x.w = v.w + p.w;
        ((float4*)xs)[i] = x;
    }
    __syncthreads();

    const int dg = t & 31;
    const int gq = t >> 5;

    float acc[4][4];
#pragma unroll
    for (int gi = 0; gi < 4; ++gi)
#pragma unroll
        for (int j = 0; j < 4; ++j) acc[gi][j] = 0.f;

#pragma unroll 4
    for (int k = 0; k < D; ++k) {
        const float* wr = wt_s + k * D + dg;
        float w0 = wr[0], w1 = wr[32], w2 = wr[64], w3 = wr[96];
#pragma unroll
        for (int gi = 0; gi < 4; ++gi) {
            float x = xs[(gq * 4 + gi) * D + k];
            acc[gi][0] += w0 * x;
            acc[gi][1] += w1 * x;
            acc[gi][2] += w2 * x;
            acc[gi][3] += w3 * x;
        }
    }

#pragma unroll
    for (int gi = 0; gi < 4; ++gi) {
        int m = m0 + gq * 4 + gi;
#pragma unroll
        for (int j = 0; j < 4; ++j) {
            int d = dg + 32 * j;
            float vh = vn_h[(long long)m * D + d];
            vn_out[(long long)m * D + d] = vh + fmaxf(acc[gi][j] + b[d], 0.f);
        }
    }
}

// ---------------------------------------------------------------------------
// Broadcast add: h_new[i,:] = h[i,:] + vn_new[seg[i],:]. One float4/thread.
// Streaming hints on the 1GB h stream keep vn_new + seg L2-resident.
__global__ void __launch_bounds__(256) broadcast_add_kernel(
    const float* __restrict__ h, const void* __restrict__ seg,
    const float* __restrict__ vn_new, float* __restrict__ h_out,
    long long total4)
{
    long long i = (long long)blockIdx.x * blockDim.x + threadIdx.x;
    if (i >= total4) return;
    const int is64 = g_seg_is_64;
    long long row = i >> 5;     // 32 float4 per row
    int c = (int)(i & 31);
    long long s = load_seg_w(seg, row, is64);

    float4 hv = __ldcs(((const float4*)h) + i);
    float4 vv = ((const float4*)vn_new)[s * 32 + c];
    hv.x += vv.x; hv.y += vv.y; hv.z += vv.z; hv.w += vv.w;
    __stcs(((float4*)h_out) + i, hv);
}

// ---------------------------------------------------------------------------
extern "C" void kernel_launch(void* const* d_in, const int* in_sizes, int n_in,
                              void* d_out, int out_size)
{
    const float* h    = (const float*)d_in[0];
    const float* vn_h = (const float*)d_in[1];
    const void*  seg  = d_in[2];
    const float* W    = (const float*)d_in[3];
    const float* b    = (const float*)d_in[4];

    const int n = in_sizes[0] / D;                 // 1,000,000 nodes

    float* h_out  = (float*)d_out;
    float* vn_out = (float*)d_out + (long long)n * D;

    prep_kernel<<<81, 256>>>(seg, W, n);

    seg_sum_kernel<<<MGRAPHS, 256>>>(h);

    static int smem_set = 0;
    const int smem_bytes = (D * D + GPB * D) * (int)sizeof(float);
    if (!smem_set) {
        cudaFuncSetAttribute(vn_fc_kernel,
                             cudaFuncAttributeMaxDynamicSharedMemorySize,
                             smem_bytes);
        smem_set = 1;
    }
    vn_fc_kernel<<<MGRAPHS / GPB, 256, smem_bytes>>>(vn_h, b, vn_out);

    long long total4 = (long long)n * (D / 4);
    int bblocks = (int)((total4 + 255) / 256);
    broadcast_add_kernel<<<bblocks, 256>>>(h, seg, vn_out, h_out, total4);
}